// round 13
// baseline (speedup 1.0000x reference)
#include <cuda_runtime.h>
#include <cuda_fp16.h>
#include <cstdint>

// ---------------- problem constants ----------------
#define DD   1024
#define EE   8
#define HH   4096
#define OO   1024
#define NTOK 4096
#define NPAIR (NTOK * 2)
#define ROWS_CAP 9240                 // 77 tiles * 120 rows

// ---------------- GEMM tile config ----------------
#define BM 120       // 96 tensor rows + 24 fma rows
#define TROWS 96
#define BN 128
#define BK 32
#define RWA 36       // A smem pitch (u32); 144B rows, 16B-aligned
#define RWB 136      // B smem pitch (u32); 544B rows

// ---------------- asm helpers ----------------
__device__ __forceinline__ void mma_tf32(float* c, const uint32_t* a, const uint32_t* b) {
    asm volatile("mma.sync.aligned.m16n8k8.row.col.f32.tf32.tf32.f32 "
                 "{%0,%1,%2,%3}, {%4,%5,%6,%7}, {%8,%9}, {%0,%1,%2,%3};"
                 : "+f"(c[0]), "+f"(c[1]), "+f"(c[2]), "+f"(c[3])
                 : "r"(a[0]), "r"(a[1]), "r"(a[2]), "r"(a[3]), "r"(b[0]), "r"(b[1]));
}
__device__ __forceinline__ uint32_t f2tf32(float v) {
    uint32_t r;
    asm("cvt.rna.tf32.f32 %0, %1;" : "=r"(r) : "f"(v));
    return r;
}
__device__ __forceinline__ uint4 cvt4(float4 v) {
    uint4 o;
    o.x = f2tf32(v.x); o.y = f2tf32(v.y);
    o.z = f2tf32(v.z); o.w = f2tf32(v.w);
    return o;
}
__device__ __forceinline__ uint32_t f2h2(float lo, float hi) {
    __half2 h = __floats2half2_rn(lo, hi);
    return *(uint32_t*)&h;
}

// ---------------- scratch (static device globals; device-code access ONLY) ----------------
__device__ int   g_counts[EE];
__device__ int   g_cursor[EE];
__device__ int   g_off[EE + 1];
__device__ int   g_top_idx[NPAIR];
__device__ float g_top_w[NPAIR];
__device__ int   g_row_token[ROWS_CAP];
__device__ int   g_row_of_pair[NPAIR];
__device__ __align__(16) __half g_hf16[(size_t)ROWS_CAP * HH];   // hidden, fp16
__device__ __align__(16) float  g_y[(size_t)ROWS_CAP * OO];

// ---------------- small kernels ----------------
__global__ void router_kernel(const float* __restrict__ x,
                              const float* __restrict__ Wg,
                              const float* __restrict__ bg) {
    __shared__ float sWg[DD * EE];
    int tid = threadIdx.x;
    for (int i = tid * 4; i < DD * EE; i += blockDim.x * 4)
        *(float4*)&sWg[i] = *(const float4*)&Wg[i];
    __syncthreads();

    int warp = tid >> 5, lane = tid & 31;
    int n = blockIdx.x * 8 + warp;
    const float* xr = x + (size_t)n * DD;

    float acc[EE];
#pragma unroll
    for (int e = 0; e < EE; e++) acc[e] = 0.f;
    for (int d = lane; d < DD; d += 32) {
        float xv = xr[d];
#pragma unroll
        for (int e = 0; e < EE; e++) acc[e] += xv * sWg[d * EE + e];
    }
#pragma unroll
    for (int e = 0; e < EE; e++)
#pragma unroll
        for (int s = 16; s; s >>= 1) acc[e] += __shfl_xor_sync(0xffffffffu, acc[e], s);

    if (lane == 0) {
        float m = -1e30f;
#pragma unroll
        for (int e = 0; e < EE; e++) { acc[e] += bg[e]; m = fmaxf(m, acc[e]); }
        float s = 0.f;
#pragma unroll
        for (int e = 0; e < EE; e++) { acc[e] = __expf(acc[e] - m); s += acc[e]; }
        float inv = 1.f / s;
        int i0 = 0; float p0 = acc[0];
#pragma unroll
        for (int e = 1; e < EE; e++) if (acc[e] > p0) { p0 = acc[e]; i0 = e; }
        int i1 = -1; float p1 = -1.f;
#pragma unroll
        for (int e = 0; e < EE; e++) if (e != i0 && acc[e] > p1) { p1 = acc[e]; i1 = e; }

        g_top_idx[2 * n]     = i0; g_top_w[2 * n]     = p0 * inv;
        g_top_idx[2 * n + 1] = i1; g_top_w[2 * n + 1] = p1 * inv;
        atomicAdd(&g_counts[i0], 1);
        atomicAdd(&g_counts[i1], 1);
    }
}

__global__ void scan_kernel() {
    int off = 0;
    for (int e = 0; e < EE; e++) {
        g_off[e] = off;
        g_cursor[e] = off;
        off += ((g_counts[e] + BM - 1) / BM) * BM;   // 120-aligned capacity
    }
    g_off[EE] = off;
}

__global__ void scatter_kernel() {
    int p = blockIdx.x * blockDim.x + threadIdx.x;
    if (p >= NPAIR) return;
    int e = g_top_idx[p];
    int pos = atomicAdd(&g_cursor[e], 1);
    g_row_token[pos] = p >> 1;
    g_row_of_pair[p] = pos;
}

// ---------------- hybrid grouped GEMM: 96 tensor rows + 24 FFMA rows ----------------
// Single tf32-rounded operand staging (sA [m][k], sB [k][n]); warps 0-3 run
// tf32 MMA on rows 0-95, warps 4-7 run fp32 FFMA on rows 96-119 (one of each
// per SMSP -> tensor + fma pipes run concurrently, each exactly 1536 cyc/chunk).
template <int KTOT, int NOUTT, bool G1>
__global__ __launch_bounds__(256, 1) void moe_gemm(const float* __restrict__ xArg,
                                                   const float* __restrict__ Barg,
                                                   const float* __restrict__ bias) {
    constexpr int NOUT = NOUTT;

    __shared__ __align__(16) uint32_t sA[BM][RWA];     // [m][k] tf32-rounded fp32
    __shared__ __align__(16) uint32_t sB[BK][RWB];     // [k][n] tf32-rounded fp32
    __shared__ int stok[BM];

    const int tid = threadIdx.x;
    const int row0 = blockIdx.y * BM;
    if (row0 >= g_off[EE]) return;
    int e = 0;
#pragma unroll
    for (int i = 1; i < EE; i++) if (row0 >= g_off[i]) e = i;
    const int valid = g_off[e] + g_counts[e] - row0;
    const int n0 = blockIdx.x * BN;
    const float* __restrict__ Bbase = Barg + (size_t)e * KTOT * NOUT + n0;

    if (G1) {
        if (tid < BM) stok[tid] = (tid < valid) ? g_row_token[row0 + tid] : -1;
        __syncthreads();
    }

    // ---- loader slots ----
    // G1 A (fp32 gather): 960 slots (120 rows x 8 float4 chunks); 4/thread guarded
    const float* aF[4]; uint32_t* adF[4]; bool aokF[4];
    // G2 A (fp16 rows): 480 slots (120 rows x 4 eight-half chunks); 2/thread guarded
    const __half* aH[2]; uint32_t* adH[2]; bool aokH[2];
    if (G1) {
#pragma unroll
        for (int j = 0; j < 4; j++) {
            int id = tid + 256 * j;
            bool act = (id < 960);
            int r = act ? (id >> 3) : 0;
            int ch = id & 7;
            int tk = stok[r];
            aokF[j] = act && (tk >= 0);
            long ar = (tk >= 0) ? tk : 0;
            aF[j] = xArg + (size_t)ar * KTOT + ch * 4;
            adF[j] = act ? &sA[r][ch * 4] : nullptr;
        }
    } else {
#pragma unroll
        for (int j = 0; j < 2; j++) {
            int id = tid + 256 * j;
            bool act = (id < 480);
            int r = act ? (id >> 2) : 0;
            int c8 = id & 3;
            aokH[j] = act;
            aH[j] = g_hf16 + (size_t)(row0 + r) * KTOT + c8 * 8;
            adH[j] = act ? &sA[r][c8 * 8] : nullptr;
        }
    }
    // B slots: 1024 (32 k-rows x 32 float4 chunks); 4/thread
    const float* bsrc[4]; uint32_t* bdst[4];
#pragma unroll
    for (int j = 0; j < 4; j++) {
        int id = tid + 256 * j;
        int kq = id >> 5, nq = id & 31;
        bsrc[j] = Bbase + (size_t)kq * NOUT + nq * 4;
        bdst[j] = &sB[kq][nq * 4];
    }

    const int lane = tid & 31, wid = tid >> 5;
    const bool isTensor = (wid < 4);
    const int gid = lane >> 2, tg = lane & 3;
    // tensor warp tile: 48 x 64
    const int wm = (wid >> 1) * 48, wn = (wid & 1) * 64;
    // fma warp rows: 96 + (wid-4)*6, cols lane*4 .. lane*4+3
    const int fr0 = TROWS + (wid - 4) * 6;

    float acc[3][8][4];      // tensor accumulators (96)
    float acc2[6][4];        // fma accumulators (24)
    if (isTensor) {
#pragma unroll
        for (int i = 0; i < 3; i++)
#pragma unroll
            for (int j = 0; j < 8; j++)
#pragma unroll
                for (int q = 0; q < 4; q++) acc[i][j][q] = 0.f;
    } else {
#pragma unroll
        for (int i = 0; i < 6; i++)
#pragma unroll
            for (int j = 0; j < 4; j++) acc2[i][j] = 0.f;
    }

    const int NC = KTOT / BK;
    const float4 zf4 = make_float4(0.f, 0.f, 0.f, 0.f);
    float4 paF[4]; uint4 paH[2]; float4 pb[4];
    if (G1) {
#pragma unroll
        for (int j = 0; j < 4; j++) paF[j] = aokF[j] ? *(const float4*)aF[j] : zf4;
    } else {
#pragma unroll
        for (int j = 0; j < 2; j++) if (aokH[j]) paH[j] = *(const uint4*)aH[j];
    }
#pragma unroll
    for (int j = 0; j < 4; j++) pb[j] = *(const float4*)bsrc[j];

#pragma unroll 1
    for (int c = 0; c < NC; c++) {
        __syncthreads();
        if (G1) {
#pragma unroll
            for (int j = 0; j < 4; j++) if (adF[j]) *(uint4*)adF[j] = cvt4(paF[j]);
        } else {
#pragma unroll
            for (int j = 0; j < 2; j++) if (adH[j]) {
                __half2 h0 = *(__half2*)&paH[j].x;
                __half2 h1 = *(__half2*)&paH[j].y;
                __half2 h2 = *(__half2*)&paH[j].z;
                __half2 h3 = *(__half2*)&paH[j].w;
                float2 f0 = __half22float2(h0);
                float2 f1 = __half22float2(h1);
                float2 f2 = __half22float2(h2);
                float2 f3 = __half22float2(h3);
                uint4 lo, hi;
                lo.x = __float_as_uint(f0.x); lo.y = __float_as_uint(f0.y);
                lo.z = __float_as_uint(f1.x); lo.w = __float_as_uint(f1.y);
                hi.x = __float_as_uint(f2.x); hi.y = __float_as_uint(f2.y);
                hi.z = __float_as_uint(f3.x); hi.w = __float_as_uint(f3.y);
                *(uint4*)adH[j] = lo;
                *(uint4*)(adH[j] + 4) = hi;
            }
        }
#pragma unroll
        for (int j = 0; j < 4; j++) *(uint4*)bdst[j] = cvt4(pb[j]);
        __syncthreads();
        if (c + 1 < NC) {
            size_t ko = (size_t)(c + 1) * BK;
            if (G1) {
#pragma unroll
                for (int j = 0; j < 4; j++)
                    paF[j] = aokF[j] ? *(const float4*)(aF[j] + ko) : zf4;
            } else {
#pragma unroll
                for (int j = 0; j < 2; j++) if (aokH[j]) paH[j] = *(const uint4*)(aH[j] + ko);
            }
#pragma unroll
            for (int j = 0; j < 4; j++) pb[j] = *(const float4*)(bsrc[j] + ko * NOUT);
        }
        if (isTensor) {
#pragma unroll
            for (int kk = 0; kk < 4; kk++) {
                const int kb = kk * 8;
                uint32_t af[3][4];
#pragma unroll
                for (int mt = 0; mt < 3; mt++) {
                    int r = wm + mt * 16 + gid;
                    af[mt][0] = sA[r][kb + tg];
                    af[mt][1] = sA[r + 8][kb + tg];
                    af[mt][2] = sA[r][kb + 4 + tg];
                    af[mt][3] = sA[r + 8][kb + 4 + tg];
                }
                uint32_t bf[8][2];
#pragma unroll
                for (int nt = 0; nt < 8; nt++) {
                    int n = wn + nt * 8 + gid;
                    bf[nt][0] = sB[kb + tg][n];
                    bf[nt][1] = sB[kb + 4 + tg][n];
                }
#pragma unroll
                for (int mt = 0; mt < 3; mt++)
#pragma unroll
                    for (int nt = 0; nt < 8; nt++)
                        mma_tf32(acc[mt][nt], af[mt], bf[nt]);
            }
        } else {
#pragma unroll 4
            for (int k = 0; k < BK; k++) {
                uint4 q = *(const uint4*)&sB[k][lane * 4];
                float bv[4] = {__uint_as_float(q.x), __uint_as_float(q.y),
                               __uint_as_float(q.z), __uint_as_float(q.w)};
#pragma unroll
                for (int r = 0; r < 6; r++) {
                    float av = __uint_as_float(sA[fr0 + r][k]);
#pragma unroll
                    for (int cc = 0; cc < 4; cc++)
                        acc2[r][cc] = fmaf(av, bv[cc], acc2[r][cc]);
                }
            }
        }
    }

    // ---------------- epilogue ----------------
    if (isTensor) {
#pragma unroll
        for (int mt = 0; mt < 3; mt++) {
#pragma unroll
            for (int nt = 0; nt < 8; nt++) {
                int mm = wm + mt * 16 + gid;
                int m = row0 + mm;
                int n = n0 + wn + nt * 8 + 2 * tg;
                float b0 = bias[(size_t)e * NOUT + n];
                float b1v = bias[(size_t)e * NOUT + n + 1];
                float z00 = acc[mt][nt][0] + b0, z01 = acc[mt][nt][1] + b1v;
                float z10 = acc[mt][nt][2] + b0, z11 = acc[mt][nt][3] + b1v;
                if (G1) {
                    z00 = fmaxf(z00, 0.f); z01 = fmaxf(z01, 0.f);
                    z10 = fmaxf(z10, 0.f); z11 = fmaxf(z11, 0.f);
                    if (mm < valid)
                        *(uint32_t*)(g_hf16 + (size_t)m * NOUT + n) = f2h2(z00, z01);
                    if (mm + 8 < valid)
                        *(uint32_t*)(g_hf16 + (size_t)(m + 8) * NOUT + n) = f2h2(z10, z11);
                } else {
                    if (mm < valid)
                        *(float2*)(g_y + (size_t)m * NOUT + n) = make_float2(z00, z01);
                    if (mm + 8 < valid)
                        *(float2*)(g_y + (size_t)(m + 8) * NOUT + n) = make_float2(z10, z11);
                }
            }
        }
    } else {
#pragma unroll
        for (int r = 0; r < 6; r++) {
            int mm = fr0 + r;
            if (mm >= valid) continue;
            int m = row0 + mm;
            int n = n0 + lane * 4;
            float b0 = bias[(size_t)e * NOUT + n];
            float b1 = bias[(size_t)e * NOUT + n + 1];
            float b2 = bias[(size_t)e * NOUT + n + 2];
            float b3 = bias[(size_t)e * NOUT + n + 3];
            float z0 = acc2[r][0] + b0, z1 = acc2[r][1] + b1;
            float z2 = acc2[r][2] + b2, z3 = acc2[r][3] + b3;
            if (G1) {
                z0 = fmaxf(z0, 0.f); z1 = fmaxf(z1, 0.f);
                z2 = fmaxf(z2, 0.f); z3 = fmaxf(z3, 0.f);
                uint2 o; o.x = f2h2(z0, z1); o.y = f2h2(z2, z3);
                *(uint2*)(g_hf16 + (size_t)m * NOUT + n) = o;
            } else {
                *(float4*)(g_y + (size_t)m * NOUT + n) = make_float4(z0, z1, z2, z3);
            }
        }
    }
}

// ---------------- combine (also resets counts for next graph replay) ----------------
__global__ void combine_kernel(float* __restrict__ out) {
    int n = blockIdx.x;
    int r0 = g_row_of_pair[2 * n];
    int r1 = g_row_of_pair[2 * n + 1];
    float w0 = g_top_w[2 * n];
    float w1 = g_top_w[2 * n + 1];
    const float4* y0 = (const float4*)&g_y[(size_t)r0 * OO];
    const float4* y1 = (const float4*)&g_y[(size_t)r1 * OO];
    float4* o = (float4*)&out[(size_t)n * OO];
    int t = threadIdx.x;
    float4 a = y0[t], b = y1[t];
    float4 r;
    r.x = w0 * a.x + w1 * b.x;
    r.y = w0 * a.y + w1 * b.y;
    r.z = w0 * a.z + w1 * b.z;
    r.w = w0 * a.w + w1 * b.w;
    o[t] = r;
    if (n == 0 && t < EE) g_counts[t] = 0;   // .bss starts zero; invariant per call
}

// ---------------- launch ----------------
extern "C" void kernel_launch(void* const* d_in, const int* in_sizes, int n_in,
                              void* d_out, int out_size) {
    const float* x  = (const float*)d_in[0];
    const float* Wg = (const float*)d_in[1];
    const float* bg = (const float*)d_in[2];
    const float* W1 = (const float*)d_in[3];
    const float* b1 = (const float*)d_in[4];
    const float* W2 = (const float*)d_in[5];
    const float* b2 = (const float*)d_in[6];
    float* out = (float*)d_out;

    router_kernel<<<NTOK / 8, 256>>>(x, Wg, bg);
    scan_kernel<<<1, 1>>>();
    scatter_kernel<<<NPAIR / 256, 256>>>();

    moe_gemm<DD, HH, true><<<dim3(HH / BN, ROWS_CAP / BM), 256>>>(x, W1, b1);
    moe_gemm<HH, OO, false><<<dim3(OO / BN, ROWS_CAP / BM), 256>>>(x, W2, b2);

    combine_kernel<<<NTOK, 256>>>(out);
}

// round 14
// speedup vs baseline: 1.4417x; 1.4417x over previous
#include <cuda_runtime.h>
#include <cuda_fp16.h>
#include <cstdint>

// ---------------- problem constants ----------------
#define DD   1024
#define EE   8
#define HH   4096
#define OO   1024
#define NTOK 4096
#define NPAIR (NTOK * 2)
#define ROWS_CAP (NPAIR + EE * 128)   // 9216

// ---------------- GEMM tile config ----------------
#define BM 128
#define BN 128
#define BK 32
#define RWA 36       // A smem pitch (u32): frag loads conflict-free
#define RWB 136      // B smem pitch (u32): 136%32==8 -> frag loads conflict-free

// ---------------- asm helpers ----------------
__device__ __forceinline__ void mma_tf32(float* c, const uint32_t* a, const uint32_t* b) {
    asm volatile("mma.sync.aligned.m16n8k8.row.col.f32.tf32.tf32.f32 "
                 "{%0,%1,%2,%3}, {%4,%5,%6,%7}, {%8,%9}, {%0,%1,%2,%3};"
                 : "+f"(c[0]), "+f"(c[1]), "+f"(c[2]), "+f"(c[3])
                 : "r"(a[0]), "r"(a[1]), "r"(a[2]), "r"(a[3]), "r"(b[0]), "r"(b[1]));
}
__device__ __forceinline__ uint32_t f2tf32(float v) {
    uint32_t r;
    asm("cvt.rna.tf32.f32 %0, %1;" : "=r"(r) : "f"(v));
    return r;
}
__device__ __forceinline__ uint4 cvt4(float4 v) {
    uint4 o;
    o.x = f2tf32(v.x); o.y = f2tf32(v.y);
    o.z = f2tf32(v.z); o.w = f2tf32(v.w);
    return o;
}
__device__ __forceinline__ uint32_t f2h2(float lo, float hi) {
    __half2 h = __floats2half2_rn(lo, hi);
    return *(uint32_t*)&h;
}

// ---------------- scratch (static device globals; device-code access ONLY) ----------------
__device__ int   g_counts[EE];
__device__ int   g_cursor[EE];
__device__ int   g_off[EE + 1];
__device__ int   g_top_idx[NPAIR];
__device__ float g_top_w[NPAIR];
__device__ int   g_row_token[ROWS_CAP];
__device__ int   g_row_of_pair[NPAIR];
__device__ __align__(16) __half g_hf16[(size_t)ROWS_CAP * HH];   // hidden, fp16
__device__ __align__(16) float  g_y[(size_t)ROWS_CAP * OO];

// ---------------- small kernels ----------------
__global__ void router_kernel(const float* __restrict__ x,
                              const float* __restrict__ Wg,
                              const float* __restrict__ bg) {
    __shared__ float sWg[DD * EE];
    int tid = threadIdx.x;
    for (int i = tid * 4; i < DD * EE; i += blockDim.x * 4)
        *(float4*)&sWg[i] = *(const float4*)&Wg[i];
    __syncthreads();

    int warp = tid >> 5, lane = tid & 31;
    int n = blockIdx.x * 8 + warp;
    const float* xr = x + (size_t)n * DD;

    float acc[EE];
#pragma unroll
    for (int e = 0; e < EE; e++) acc[e] = 0.f;
    for (int d = lane; d < DD; d += 32) {
        float xv = xr[d];
#pragma unroll
        for (int e = 0; e < EE; e++) acc[e] += xv * sWg[d * EE + e];
    }
#pragma unroll
    for (int e = 0; e < EE; e++)
#pragma unroll
        for (int s = 16; s; s >>= 1) acc[e] += __shfl_xor_sync(0xffffffffu, acc[e], s);

    if (lane == 0) {
        float m = -1e30f;
#pragma unroll
        for (int e = 0; e < EE; e++) { acc[e] += bg[e]; m = fmaxf(m, acc[e]); }
        float s = 0.f;
#pragma unroll
        for (int e = 0; e < EE; e++) { acc[e] = __expf(acc[e] - m); s += acc[e]; }
        float inv = 1.f / s;
        int i0 = 0; float p0 = acc[0];
#pragma unroll
        for (int e = 1; e < EE; e++) if (acc[e] > p0) { p0 = acc[e]; i0 = e; }
        int i1 = -1; float p1 = -1.f;
#pragma unroll
        for (int e = 0; e < EE; e++) if (e != i0 && acc[e] > p1) { p1 = acc[e]; i1 = e; }

        g_top_idx[2 * n]     = i0; g_top_w[2 * n]     = p0 * inv;
        g_top_idx[2 * n + 1] = i1; g_top_w[2 * n + 1] = p1 * inv;
        atomicAdd(&g_counts[i0], 1);
        atomicAdd(&g_counts[i1], 1);
    }
}

__global__ void scan_kernel() {
    int off = 0;
    for (int e = 0; e < EE; e++) {
        g_off[e] = off;
        g_cursor[e] = off;
        off += (g_counts[e] + 127) & ~127;
    }
    g_off[EE] = off;
}

__global__ void scatter_kernel() {
    int p = blockIdx.x * blockDim.x + threadIdx.x;
    if (p >= NPAIR) return;
    int e = g_top_idx[p];
    int pos = atomicAdd(&g_cursor[e], 1);
    g_row_token[pos] = p >> 1;
    g_row_of_pair[p] = pos;
}

// ---------------- TF32 grouped GEMM, fused on-the-fly rounding ----------------
// B (fp32 weights [E][K][N], N contiguous) read raw, tf32-rounded at smem store,
// staged [k][n] pitch 136. A: GEMM1 = gathered fp32 x (tf32 cvt at store);
// GEMM2 = fp16 hidden rows (exact cvt to fp32 = already tf32-representable).
// GEMM1 out: relu -> fp16 g_hf16.  GEMM2 out: fp32 g_y.
// M-strips entirely past `valid` skip their MMAs (uniform predicate).
template <int KTOT, int NOUTT, bool G1>
__global__ __launch_bounds__(256, 1) void moe_gemm(const float* __restrict__ xArg,
                                                   const float* __restrict__ Barg,
                                                   const float* __restrict__ bias) {
    const int NOUT = NOUTT;

    __shared__ __align__(16) uint32_t sA[BM][RWA];     // [m][k] fp32(tf32)
    __shared__ __align__(16) uint32_t sB[BK][RWB];     // [k][n] fp32(tf32)
    __shared__ int stok[BM];

    const int tid = threadIdx.x;
    const int row0 = blockIdx.y * BM;
    if (row0 >= g_off[EE]) return;
    int e = 0;
#pragma unroll
    for (int i = 1; i < EE; i++) if (row0 >= g_off[i]) e = i;
    const int valid = g_off[e] + g_counts[e] - row0;
    const int n0 = blockIdx.x * BN;
    const float* __restrict__ Bbase = Barg + (size_t)e * KTOT * NOUT + n0;

    if (G1) {
        if (tid < BM) stok[tid] = (tid < valid) ? g_row_token[row0 + tid] : -1;
        __syncthreads();
    }

    // ---- loader slots ----
    const float* aF[4]; uint32_t* adF[4]; bool aok[4];
    const __half* aH[2]; uint32_t* adH[2];
    if (G1) {
#pragma unroll
        for (int j = 0; j < 4; j++) {
            int id = tid + 256 * j;
            int r = id >> 3, ch = id & 7;
            int tk = stok[r];
            aok[j] = (tk >= 0);
            long ar = aok[j] ? tk : 0;
            aF[j] = xArg + (size_t)ar * KTOT + ch * 4;
            adF[j] = &sA[r][ch * 4];
        }
    } else {
#pragma unroll
        for (int j = 0; j < 2; j++) {
            int id = tid + 256 * j;
            int r = id >> 2, c8 = id & 3;
            aH[j] = g_hf16 + (size_t)(row0 + r) * KTOT + c8 * 8;
            adH[j] = &sA[r][c8 * 8];
        }
    }
    const float* bsrc[4]; uint32_t* bdst[4];
#pragma unroll
    for (int j = 0; j < 4; j++) {
        int id = tid + 256 * j;
        int kq = id >> 5, nq = id & 31;
        bsrc[j] = Bbase + (size_t)kq * NOUT + nq * 4;
        bdst[j] = &sB[kq][nq * 4];
    }

    const int lane = tid & 31, wid = tid >> 5;
    const int wm = (wid >> 2) * 64, wn = (wid & 3) * 32;
    const int gid = lane >> 2, tg = lane & 3;

    // uniform per-warp strip predicates: strip mt covers rows [wm+16mt, wm+16mt+16)
    bool doM[4];
#pragma unroll
    for (int mt = 0; mt < 4; mt++) doM[mt] = (wm + mt * 16) < valid;

    float acc[4][4][4];
#pragma unroll
    for (int i = 0; i < 4; i++)
#pragma unroll
        for (int j = 0; j < 4; j++)
#pragma unroll
            for (int q = 0; q < 4; q++) acc[i][j][q] = 0.f;

    const int NC = KTOT / BK;
    const float4 zf4 = make_float4(0.f, 0.f, 0.f, 0.f);
    float4 paF[4]; uint4 paH[2]; float4 pb[4];
    if (G1) {
#pragma unroll
        for (int j = 0; j < 4; j++) paF[j] = aok[j] ? *(const float4*)aF[j] : zf4;
    } else {
#pragma unroll
        for (int j = 0; j < 2; j++) paH[j] = *(const uint4*)aH[j];
    }
#pragma unroll
    for (int j = 0; j < 4; j++) pb[j] = *(const float4*)bsrc[j];

#pragma unroll 1
    for (int c = 0; c < NC; c++) {
        __syncthreads();   // previous iter's smem reads done before overwrite
        if (G1) {
#pragma unroll
            for (int j = 0; j < 4; j++) *(uint4*)adF[j] = cvt4(paF[j]);
        } else {
#pragma unroll
            for (int j = 0; j < 2; j++) {
                __half2 h0 = *(__half2*)&paH[j].x;
                __half2 h1 = *(__half2*)&paH[j].y;
                __half2 h2 = *(__half2*)&paH[j].z;
                __half2 h3 = *(__half2*)&paH[j].w;
                float2 f0 = __half22float2(h0);
                float2 f1 = __half22float2(h1);
                float2 f2 = __half22float2(h2);
                float2 f3 = __half22float2(h3);
                uint4 lo, hi;
                lo.x = __float_as_uint(f0.x); lo.y = __float_as_uint(f0.y);
                lo.z = __float_as_uint(f1.x); lo.w = __float_as_uint(f1.y);
                hi.x = __float_as_uint(f2.x); hi.y = __float_as_uint(f2.y);
                hi.z = __float_as_uint(f3.x); hi.w = __float_as_uint(f3.y);
                *(uint4*)adH[j] = lo;
                *(uint4*)(adH[j] + 4) = hi;
            }
        }
#pragma unroll
        for (int j = 0; j < 4; j++) *(uint4*)bdst[j] = cvt4(pb[j]);
        __syncthreads();
        if (c + 1 < NC) {  // prefetch next K-slab into regs (hidden by MMAs)
            size_t ko = (size_t)(c + 1) * BK;
            if (G1) {
#pragma unroll
                for (int j = 0; j < 4; j++)
                    paF[j] = aok[j] ? *(const float4*)(aF[j] + ko) : zf4;
            } else {
#pragma unroll
                for (int j = 0; j < 2; j++) paH[j] = *(const uint4*)(aH[j] + ko);
            }
#pragma unroll
            for (int j = 0; j < 4; j++) pb[j] = *(const float4*)(bsrc[j] + ko * NOUT);
        }
#pragma unroll
        for (int kk = 0; kk < 4; kk++) {
            const int kb = kk * 8;   // 8 fp32 = K8 per mma step
            uint32_t bf[4][2];
#pragma unroll
            for (int nt = 0; nt < 4; nt++) {
                int n = wn + nt * 8 + gid;
                bf[nt][0] = sB[kb + tg][n];
                bf[nt][1] = sB[kb + 4 + tg][n];
            }
#pragma unroll
            for (int mt = 0; mt < 4; mt++) {
                if (doM[mt]) {     // uniform branch; skip dead padding strips
                    uint32_t af[4];
                    int r = wm + mt * 16 + gid;
                    af[0] = sA[r][kb + tg];
                    af[1] = sA[r + 8][kb + tg];
                    af[2] = sA[r][kb + 4 + tg];
                    af[3] = sA[r + 8][kb + 4 + tg];
#pragma unroll
                    for (int nt = 0; nt < 4; nt++)
                        mma_tf32(acc[mt][nt], af, bf[nt]);
                }
            }
        }
    }

    // ---------------- epilogue (C frag: c0/c1 row gid cols 2tg,2tg+1; c2/c3 row gid+8) ----------------
#pragma unroll
    for (int mt = 0; mt < 4; mt++) {
        if (!doM[mt]) continue;
#pragma unroll
        for (int nt = 0; nt < 4; nt++) {
            int mm = wm + mt * 16 + gid;          // block-local row
            int m = row0 + mm;
            int n = n0 + wn + nt * 8 + 2 * tg;
            float b0 = bias[(size_t)e * NOUT + n];
            float b1v = bias[(size_t)e * NOUT + n + 1];
            float z00 = acc[mt][nt][0] + b0, z01 = acc[mt][nt][1] + b1v;
            float z10 = acc[mt][nt][2] + b0, z11 = acc[mt][nt][3] + b1v;
            if (G1) {
                z00 = fmaxf(z00, 0.f); z01 = fmaxf(z01, 0.f);
                z10 = fmaxf(z10, 0.f); z11 = fmaxf(z11, 0.f);
                if (mm < valid)
                    *(uint32_t*)(g_hf16 + (size_t)m * NOUT + n) = f2h2(z00, z01);
                if (mm + 8 < valid)
                    *(uint32_t*)(g_hf16 + (size_t)(m + 8) * NOUT + n) = f2h2(z10, z11);
            } else {
                if (mm < valid)
                    *(float2*)(g_y + (size_t)m * NOUT + n) = make_float2(z00, z01);
                if (mm + 8 < valid)
                    *(float2*)(g_y + (size_t)(m + 8) * NOUT + n) = make_float2(z10, z11);
            }
        }
    }
}

// ---------------- combine (also resets counts for the next launch/replay) ----------------
__global__ void combine_kernel(float* __restrict__ out) {
    int n = blockIdx.x;
    int r0 = g_row_of_pair[2 * n];
    int r1 = g_row_of_pair[2 * n + 1];
    float w0 = g_top_w[2 * n];
    float w1 = g_top_w[2 * n + 1];
    const float4* y0 = (const float4*)&g_y[(size_t)r0 * OO];
    const float4* y1 = (const float4*)&g_y[(size_t)r1 * OO];
    float4* o = (float4*)&out[(size_t)n * OO];
    int t = threadIdx.x;
    float4 a = y0[t], b = y1[t];
    float4 r;
    r.x = w0 * a.x + w1 * b.x;
    r.y = w0 * a.y + w1 * b.y;
    r.z = w0 * a.z + w1 * b.z;
    r.w = w0 * a.w + w1 * b.w;
    o[t] = r;
    if (n == 0 && t < EE) g_counts[t] = 0;   // .bss starts zero; invariant per call
}

// ---------------- launch ----------------
extern "C" void kernel_launch(void* const* d_in, const int* in_sizes, int n_in,
                              void* d_out, int out_size) {
    const float* x  = (const float*)d_in[0];
    const float* Wg = (const float*)d_in[1];
    const float* bg = (const float*)d_in[2];
    const float* W1 = (const float*)d_in[3];
    const float* b1 = (const float*)d_in[4];
    const float* W2 = (const float*)d_in[5];
    const float* b2 = (const float*)d_in[6];
    float* out = (float*)d_out;

    router_kernel<<<NTOK / 8, 256>>>(x, Wg, bg);
    scan_kernel<<<1, 1>>>();
    scatter_kernel<<<NPAIR / 256, 256>>>();

    moe_gemm<DD, HH, true><<<dim3(HH / BN, ROWS_CAP / BM), 256>>>(x, W1, b1);
    moe_gemm<HH, OO, false><<<dim3(OO / BN, ROWS_CAP / BM), 256>>>(x, W2, b2);

    combine_kernel<<<NTOK, 256>>>(out);
}